// round 2
// baseline (speedup 1.0000x reference)
#include <cuda_runtime.h>
#include <math_constants.h>

#define NROWS 8192
#define DIM   512
#define BM    128
#define BN    128
#define BK    16
#define NSPLIT 4
#define CTILES ((NROWS / BN) / NSPLIT)   // 16 column tiles per split

// Scratch (device globals: allocation-free per harness rules)
__device__ float g_x[NROWS * DIM];   // x = inputs * A
__device__ float g_sq[NROWS];        // ||x_i||^2
__device__ float g_ap2[NROWS];       // max over positives of dist^2
__device__ float g_an2[NROWS];       // min over negatives of dist^2
__device__ int   g_tstride;          // 2 if targets are int64 words, 1 if int32

// ---------------------------------------------------------------------------
// Kernel 0: detect targets layout. int64 little-endian with values in [0,64)
// => every odd 32-bit word is 0. int32 => odd words are labels (not all 0).
// ---------------------------------------------------------------------------
__global__ void detect_kernel(const int* __restrict__ tw) {
    __shared__ int red[32];
    const int t = threadIdx.x;  // 1024
    int acc = 0;
    for (int i = t; i < NROWS; i += 1024) acc |= tw[2 * i + 1];
    #pragma unroll
    for (int o = 16; o; o >>= 1) acc |= __shfl_down_sync(0xffffffffu, acc, o);
    if ((t & 31) == 0) red[t >> 5] = acc;
    __syncthreads();
    if (t < 32) {
        int v = red[t];
        #pragma unroll
        for (int o = 16; o; o >>= 1) v |= __shfl_down_sync(0xffffffffu, v, o);
        if (t == 0) g_tstride = (v == 0) ? 2 : 1;
    }
}

// ---------------------------------------------------------------------------
// Kernel 1: x = inputs .* A, row squared norms, init reduction buffers.
// ---------------------------------------------------------------------------
__global__ void prep_kernel(const float* __restrict__ in,
                            const float* __restrict__ Aw) {
    const int row = blockIdx.x;
    const int t = threadIdx.x;  // 128 threads
    const float4 a = ((const float4*)(in + (size_t)row * DIM))[t];
    const float4 b = ((const float4*)(Aw + (size_t)row * DIM))[t];
    float4 v;
    v.x = a.x * b.x; v.y = a.y * b.y; v.z = a.z * b.z; v.w = a.w * b.w;
    ((float4*)(g_x + (size_t)row * DIM))[t] = v;

    float s = v.x * v.x + v.y * v.y + v.z * v.z + v.w * v.w;
    #pragma unroll
    for (int o = 16; o; o >>= 1) s += __shfl_down_sync(0xffffffffu, s, o);

    __shared__ float red[4];
    if ((t & 31) == 0) red[t >> 5] = s;
    __syncthreads();
    if (t == 0) {
        g_sq[row]  = red[0] + red[1] + red[2] + red[3];
        g_ap2[row] = 0.0f;            // safe: equivalent post-clip(>=EPS)
        g_an2[row] = CUDART_INF_F;
    }
}

// ---------------------------------------------------------------------------
// Kernel 2: fused Gram + hard mining (dist^2 domain; sqrt deferred).
// ---------------------------------------------------------------------------
__global__ __launch_bounds__(256) void gram_kernel(const int* __restrict__ tw) {
    __shared__ float As[BK][BM + 4];
    __shared__ float Bs[BK][BN + 4];

    const int ts = g_tstride;
    const int t  = threadIdx.x;
    const int tx = t & 15, ty = t >> 4;
    const int R  = blockIdx.x * BM;
    const int m0 = ty * 8;
    const int n0 = tx * 8;

    float sqr[8]; int tr[8];
    #pragma unroll
    for (int i = 0; i < 8; ++i) {
        sqr[i] = g_sq[R + m0 + i];
        tr[i]  = tw[ts * (R + m0 + i)];
    }
    float ap2[8], an2[8];
    #pragma unroll
    for (int i = 0; i < 8; ++i) { ap2[i] = -CUDART_INF_F; an2[i] = CUDART_INF_F; }

    const int cb0 = blockIdx.y * CTILES;
    for (int cbi = 0; cbi < CTILES; ++cbi) {
        const int C = (cb0 + cbi) * BN;
        float acc[8][8];
        #pragma unroll
        for (int i = 0; i < 8; ++i)
            #pragma unroll
            for (int j = 0; j < 8; ++j) acc[i][j] = 0.f;

        for (int kb = 0; kb < DIM; kb += BK) {
            #pragma unroll
            for (int h = 0; h < 2; ++h) {
                const int f  = t + h * 256;       // 0..511
                const int m  = f >> 2;            // 0..127
                const int k4 = (f & 3) << 2;      // 0,4,8,12
                float4 va = *(const float4*)&g_x[(size_t)(R + m) * DIM + kb + k4];
                As[k4 + 0][m] = va.x; As[k4 + 1][m] = va.y;
                As[k4 + 2][m] = va.z; As[k4 + 3][m] = va.w;
                float4 vb = *(const float4*)&g_x[(size_t)(C + m) * DIM + kb + k4];
                Bs[k4 + 0][m] = vb.x; Bs[k4 + 1][m] = vb.y;
                Bs[k4 + 2][m] = vb.z; Bs[k4 + 3][m] = vb.w;
            }
            __syncthreads();
            #pragma unroll
            for (int k = 0; k < BK; ++k) {
                float a[8], b[8];
                *(float4*)&a[0] = *(const float4*)&As[k][m0];
                *(float4*)&a[4] = *(const float4*)&As[k][m0 + 4];
                *(float4*)&b[0] = *(const float4*)&Bs[k][n0];
                *(float4*)&b[4] = *(const float4*)&Bs[k][n0 + 4];
                #pragma unroll
                for (int i = 0; i < 8; ++i)
                    #pragma unroll
                    for (int j = 0; j < 8; ++j)
                        acc[i][j] = fmaf(a[i], b[j], acc[i][j]);
            }
            __syncthreads();
        }

        float sqc[8]; int tc[8];
        #pragma unroll
        for (int j = 0; j < 8; ++j) {
            sqc[j] = g_sq[C + n0 + j];
            tc[j]  = tw[ts * (C + n0 + j)];
        }
        #pragma unroll
        for (int i = 0; i < 8; ++i)
            #pragma unroll
            for (int j = 0; j < 8; ++j) {
                const float d2 = fmaf(-2.f, acc[i][j], sqr[i] + sqc[j]);
                if (tr[i] == tc[j]) ap2[i] = fmaxf(ap2[i], d2);
                else                an2[i] = fminf(an2[i], d2);
            }
    }

    // Cross-thread reduction in smem, then global int-ordered atomic merge.
    float* red = &As[0][0];   // 2112 floats >= 2048 needed
    __syncthreads();
    #pragma unroll
    for (int i = 0; i < 8; ++i) red[(m0 + i) * 16 + tx] = ap2[i];
    __syncthreads();
    if (t < 128) {
        float v = red[t * 16];
        #pragma unroll
        for (int q = 1; q < 16; ++q) v = fmaxf(v, red[t * 16 + q]);
        atomicMax((int*)&g_ap2[R + t], __float_as_int(v));
    }
    __syncthreads();
    #pragma unroll
    for (int i = 0; i < 8; ++i) red[(m0 + i) * 16 + tx] = an2[i];
    __syncthreads();
    if (t < 128) {
        float v = red[t * 16];
        #pragma unroll
        for (int q = 1; q < 16; ++q) v = fminf(v, red[t * 16 + q]);
        atomicMin((int*)&g_an2[R + t], __float_as_int(v));
    }
}

// ---------------------------------------------------------------------------
// Kernel 3: loss = mean(relu(sqrt(clip(ap2)) - sqrt(clip(an2)) + margin))
// ---------------------------------------------------------------------------
__global__ void loss_kernel(float* __restrict__ out) {
    __shared__ float red[32];
    const int t = threadIdx.x;  // 1024
    float s = 0.f;
    for (int i = t; i < NROWS; i += 1024) {
        const float ap = sqrtf(fmaxf(g_ap2[i], 1e-12f));
        const float an = sqrtf(fmaxf(g_an2[i], 1e-12f));
        s += fmaxf(ap - an + 0.5f, 0.f);
    }
    #pragma unroll
    for (int o = 16; o; o >>= 1) s += __shfl_down_sync(0xffffffffu, s, o);
    if ((t & 31) == 0) red[t >> 5] = s;
    __syncthreads();
    if (t < 32) {
        float v = red[t];
        #pragma unroll
        for (int o = 16; o; o >>= 1) v += __shfl_down_sync(0xffffffffu, v, o);
        if (t == 0) out[0] = v * (1.0f / (float)NROWS);
    }
}

// ---------------------------------------------------------------------------
extern "C" void kernel_launch(void* const* d_in, const int* in_sizes, int n_in,
                              void* d_out, int out_size) {
    const float* inputs = (const float*)d_in[0];
    const float* A      = (const float*)d_in[1];
    const int*   tw     = (const int*)d_in[2];   // int64 OR int32 words

    detect_kernel<<<1, 1024>>>(tw);
    prep_kernel<<<NROWS, 128>>>(inputs, A);
    dim3 grid(NROWS / BM, NSPLIT);
    gram_kernel<<<grid, 256>>>(tw);
    loss_kernel<<<1, 1024>>>((float*)d_out);
}

// round 5
// speedup vs baseline: 7.2113x; 7.2113x over previous
#include <cuda_runtime.h>
#include <math_constants.h>
#include <cstdint>

#define NROWS 8192
#define DIM   512
#define BT    128            // block tile (M=N)
#define BK    32             // k chunk per stage
#define NCH   (DIM / BK)     // 16
#define NB    (NROWS / BT)   // 64
#define NBLK  (NB * (NB + 1) / 2)   // 2080 upper-triangle blocks
#define LDS_  36             // padded row stride (floats)

// Scratch (device globals: allocation-free)
__device__ float g_x[NROWS * DIM];   // tf32-rounded weighted features
__device__ float g_sq[NROWS];        // ||x||^2 of ROUNDED x (consistent geometry)
__device__ float g_ap2[NROWS];
__device__ float g_an2[NROWS];
__device__ int   g_tstride;

static __device__ __forceinline__ float tf32r(float f) {
    uint32_t u;
    asm("cvt.rna.tf32.f32 %0, %1;" : "=r"(u) : "f"(f));
    return __uint_as_float(u);
}
static __device__ __forceinline__ void cp16(uint32_t s, const void* g) {
    asm volatile("cp.async.cg.shared.global [%0], [%1], 16;" :: "r"(s), "l"(g));
}
static __device__ __forceinline__ void mma_tf32(float* d, const uint32_t* a, const uint32_t* b) {
    asm volatile(
        "mma.sync.aligned.m16n8k8.row.col.f32.tf32.tf32.f32 "
        "{%0,%1,%2,%3}, {%4,%5,%6,%7}, {%8,%9}, {%0,%1,%2,%3};\n"
        : "+f"(d[0]), "+f"(d[1]), "+f"(d[2]), "+f"(d[3])
        : "r"(a[0]), "r"(a[1]), "r"(a[2]), "r"(a[3]), "r"(b[0]), "r"(b[1]));
}

// ---------------------------------------------------------------------------
__global__ void detect_kernel(const int* __restrict__ tw) {
    __shared__ int red[32];
    const int t = threadIdx.x;
    int acc = 0;
    for (int i = t; i < NROWS; i += 1024) acc |= tw[2 * i + 1];
    #pragma unroll
    for (int o = 16; o; o >>= 1) acc |= __shfl_down_sync(0xffffffffu, acc, o);
    if ((t & 31) == 0) red[t >> 5] = acc;
    __syncthreads();
    if (t < 32) {
        int v = red[t];
        #pragma unroll
        for (int o = 16; o; o >>= 1) v |= __shfl_down_sync(0xffffffffu, v, o);
        if (t == 0) g_tstride = (v == 0) ? 2 : 1;
    }
}

__global__ void prep_kernel(const float* __restrict__ in, const float* __restrict__ Aw) {
    const int row = blockIdx.x;
    const int t = threadIdx.x;  // 128
    const float4 a = ((const float4*)(in + (size_t)row * DIM))[t];
    const float4 b = ((const float4*)(Aw + (size_t)row * DIM))[t];
    float4 v;
    v.x = tf32r(a.x * b.x); v.y = tf32r(a.y * b.y);
    v.z = tf32r(a.z * b.z); v.w = tf32r(a.w * b.w);
    ((float4*)(g_x + (size_t)row * DIM))[t] = v;
    float s = v.x * v.x + v.y * v.y + v.z * v.z + v.w * v.w;
    #pragma unroll
    for (int o = 16; o; o >>= 1) s += __shfl_down_sync(0xffffffffu, s, o);
    __shared__ float red[4];
    if ((t & 31) == 0) red[t >> 5] = s;
    __syncthreads();
    if (t == 0) {
        g_sq[row]  = red[0] + red[1] + red[2] + red[3];
        g_ap2[row] = 0.0f;
        g_an2[row] = CUDART_INF_F;
    }
}

// ---------------------------------------------------------------------------
// tf32 mma.sync Gram on upper-triangle blocks, fused symmetric hard mining.
// 256 threads = 8 warps (4 in M x 2 in N); warp tile 32x64.
// ---------------------------------------------------------------------------
__global__ __launch_bounds__(256) void gram_mma(const int* __restrict__ tw) {
    extern __shared__ float smem[];
    const uint32_t sb = (uint32_t)__cvta_generic_to_shared(smem);
    // layout (floats): A stages [2][128*36] then B stages [2][128*36]
    #define ASo(s) ((s) * (BT * LDS_))
    #define BSo(s) (2 * (BT * LDS_) + (s) * (BT * LDS_))

    const int tid  = threadIdx.x;
    const int lane = tid & 31;
    const int wid  = tid >> 5;
    const int g    = lane >> 2;
    const int c    = lane & 3;
    const int warpM = (wid & 3) * 32;
    const int warpN = (wid >> 2) * 64;
    const int ts = g_tstride;

    // map linear block id -> upper triangle (bi <= bj)
    int bi = 0, rem = blockIdx.x;
    while (rem >= NB - bi) { rem -= NB - bi; ++bi; }
    const int bj = bi + rem;
    const int R = bi * BT, C = bj * BT;

    float acc[2][8][4];
    #pragma unroll
    for (int t = 0; t < 2; ++t)
        #pragma unroll
        for (int n = 0; n < 8; ++n)
            #pragma unroll
            for (int e = 0; e < 4; ++e) acc[t][n][e] = 0.f;

    auto load_stage = [&](int kb, int s) {
        const char* gb = (const char*)g_x;
        #pragma unroll
        for (int i = 0; i < 4; ++i) {
            const int q   = tid + i * 256;       // 0..1023
            const int row = q >> 3;              // 0..127
            const int ck  = q & 7;               // 16B chunk in 128B row
            const size_t gofs = ((size_t)(R + row) * DIM + kb * BK + ck * 4) * 4;
            cp16(sb + (ASo(s) + row * LDS_ + ck * 4) * 4, gb + gofs);
            const size_t gofsB = ((size_t)(C + row) * DIM + kb * BK + ck * 4) * 4;
            cp16(sb + (BSo(s) + row * LDS_ + ck * 4) * 4, gb + gofsB);
        }
    };

    load_stage(0, 0);
    asm volatile("cp.async.commit_group;");

    for (int it = 0; it < NCH; ++it) {
        const int s = it & 1;
        if (it + 1 < NCH) load_stage(it + 1, (it + 1) & 1);
        asm volatile("cp.async.commit_group;");
        asm volatile("cp.async.wait_group 1;");
        __syncthreads();

        const float* As = smem + ASo(s);
        const float* Bs = smem + BSo(s);
        #pragma unroll
        for (int kk = 0; kk < 4; ++kk) {
            const int kb = kk * 8;
            uint32_t af[2][4], bf[8][2];
            #pragma unroll
            for (int t = 0; t < 2; ++t) {
                const int r0 = warpM + t * 16 + g;
                af[t][0] = __float_as_uint(As[r0 * LDS_ + kb + c]);
                af[t][1] = __float_as_uint(As[(r0 + 8) * LDS_ + kb + c]);
                af[t][2] = __float_as_uint(As[r0 * LDS_ + kb + c + 4]);
                af[t][3] = __float_as_uint(As[(r0 + 8) * LDS_ + kb + c + 4]);
            }
            #pragma unroll
            for (int n = 0; n < 8; ++n) {
                const int nr = warpN + n * 8 + g;
                bf[n][0] = __float_as_uint(Bs[nr * LDS_ + kb + c]);
                bf[n][1] = __float_as_uint(Bs[nr * LDS_ + kb + c + 4]);
            }
            #pragma unroll
            for (int t = 0; t < 2; ++t)
                #pragma unroll
                for (int n = 0; n < 8; ++n)
                    mma_tf32(acc[t][n], af[t], bf[n]);
        }
        __syncthreads();
    }

    // ---- epilogue: symmetric fused hard mining ----
    float scj[16]; int tcj[16];
    #pragma unroll
    for (int n = 0; n < 8; ++n) {
        const int j0 = C + warpN + n * 8 + 2 * c;
        scj[2*n]   = g_sq[j0];     scj[2*n+1] = g_sq[j0 + 1];
        tcj[2*n]   = tw[ts * j0];  tcj[2*n+1] = tw[ts * (j0 + 1)];
    }
    float sqr4[4]; int tr4[4]; int rowi[4];
    #pragma unroll
    for (int t = 0; t < 2; ++t)
        #pragma unroll
        for (int p = 0; p < 2; ++p) {
            const int ri = R + warpM + t * 16 + p * 8 + g;
            rowi[t*2+p] = ri; sqr4[t*2+p] = g_sq[ri]; tr4[t*2+p] = tw[ts * ri];
        }

    float apr[4], anr[4], apc[16], anc[16];
    #pragma unroll
    for (int i = 0; i < 4; ++i)  { apr[i] = 0.f; anr[i] = CUDART_INF_F; }
    #pragma unroll
    for (int i = 0; i < 16; ++i) { apc[i] = 0.f; anc[i] = CUDART_INF_F; }

    #pragma unroll
    for (int t = 0; t < 2; ++t)
        #pragma unroll
        for (int n = 0; n < 8; ++n)
            #pragma unroll
            for (int p = 0; p < 2; ++p) {
                const int ri = t * 2 + p;
                #pragma unroll
                for (int e = 0; e < 2; ++e) {
                    const int cj = n * 2 + e;
                    const float d2 = fmaf(-2.f, acc[t][n][p * 2 + e], sqr4[ri] + scj[cj]);
                    if (tr4[ri] == tcj[cj]) {
                        apr[ri] = fmaxf(apr[ri], d2);
                        apc[cj] = fmaxf(apc[cj], d2);
                    } else {
                        anr[ri] = fminf(anr[ri], d2);
                        anc[cj] = fminf(anc[cj], d2);
                    }
                }
            }

    // row-side: reduce across c lanes (xor 1,2), then c==0 writes
    #pragma unroll
    for (int i = 0; i < 4; ++i) {
        apr[i] = fmaxf(apr[i], __shfl_xor_sync(0xffffffffu, apr[i], 1));
        apr[i] = fmaxf(apr[i], __shfl_xor_sync(0xffffffffu, apr[i], 2));
        anr[i] = fminf(anr[i], __shfl_xor_sync(0xffffffffu, anr[i], 1));
        anr[i] = fminf(anr[i], __shfl_xor_sync(0xffffffffu, anr[i], 2));
    }
    if (c == 0) {
        #pragma unroll
        for (int i = 0; i < 4; ++i) {
            atomicMax((int*)&g_ap2[rowi[i]], __float_as_int(apr[i]));
            atomicMin((int*)&g_an2[rowi[i]], __float_as_int(anr[i]));
        }
    }
    // col-side: reduce across g lanes (xor 4,8,16), then g==0 writes
    #pragma unroll
    for (int i = 0; i < 16; ++i) {
        apc[i] = fmaxf(apc[i], __shfl_xor_sync(0xffffffffu, apc[i], 4));
        apc[i] = fmaxf(apc[i], __shfl_xor_sync(0xffffffffu, apc[i], 8));
        apc[i] = fmaxf(apc[i], __shfl_xor_sync(0xffffffffu, apc[i], 16));
        anc[i] = fminf(anc[i], __shfl_xor_sync(0xffffffffu, anc[i], 4));
        anc[i] = fminf(anc[i], __shfl_xor_sync(0xffffffffu, anc[i], 8));
        anc[i] = fminf(anc[i], __shfl_xor_sync(0xffffffffu, anc[i], 16));
    }
    if (g == 0) {
        #pragma unroll
        for (int n = 0; n < 8; ++n)
            #pragma unroll
            for (int e = 0; e < 2; ++e) {
                const int j = C + warpN + n * 8 + 2 * c + e;
                atomicMax((int*)&g_ap2[j], __float_as_int(apc[n * 2 + e]));
                atomicMin((int*)&g_an2[j], __float_as_int(anc[n * 2 + e]));
            }
    }
    #undef ASo
    #undef BSo
}

// ---------------------------------------------------------------------------
__global__ void loss_kernel(float* __restrict__ out) {
    __shared__ float red[32];
    const int t = threadIdx.x;  // 1024
    float s = 0.f;
    #pragma unroll
    for (int h = 0; h < 2; ++h) {
        const int i = t * 8 + h * 4;
        const float4 ap = *(const float4*)&g_ap2[i];
        const float4 an = *(const float4*)&g_an2[i];
        s += fmaxf(sqrtf(fmaxf(ap.x, 1e-12f)) - sqrtf(fmaxf(an.x, 1e-12f)) + 0.5f, 0.f);
        s += fmaxf(sqrtf(fmaxf(ap.y, 1e-12f)) - sqrtf(fmaxf(an.y, 1e-12f)) + 0.5f, 0.f);
        s += fmaxf(sqrtf(fmaxf(ap.z, 1e-12f)) - sqrtf(fmaxf(an.z, 1e-12f)) + 0.5f, 0.f);
        s += fmaxf(sqrtf(fmaxf(ap.w, 1e-12f)) - sqrtf(fmaxf(an.w, 1e-12f)) + 0.5f, 0.f);
    }
    #pragma unroll
    for (int o = 16; o; o >>= 1) s += __shfl_down_sync(0xffffffffu, s, o);
    if ((t & 31) == 0) red[t >> 5] = s;
    __syncthreads();
    if (t < 32) {
        float v = red[t];
        #pragma unroll
        for (int o = 16; o; o >>= 1) v += __shfl_down_sync(0xffffffffu, v, o);
        if (t == 0) out[0] = v * (1.0f / (float)NROWS);
    }
}

// ---------------------------------------------------------------------------
#define SMEM_BYTES (4 * BT * LDS_ * 4)   // 73728 B

extern "C" void kernel_launch(void* const* d_in, const int* in_sizes, int n_in,
                              void* d_out, int out_size) {
    const float* inputs = (const float*)d_in[0];
    const float* A      = (const float*)d_in[1];
    const int*   tw     = (const int*)d_in[2];

    cudaFuncSetAttribute(gram_mma, cudaFuncAttributeMaxDynamicSharedMemorySize, SMEM_BYTES);

    detect_kernel<<<1, 1024>>>(tw);
    prep_kernel<<<NROWS, 128>>>(inputs, A);
    gram_mma<<<NBLK, 256, SMEM_BYTES>>>(tw);
    loss_kernel<<<1, 1024>>>((float*)d_out);
}

// round 6
// speedup vs baseline: 7.3167x; 1.0146x over previous
#include <cuda_runtime.h>
#include <math_constants.h>
#include <cstdint>

#define NROWS 8192
#define DIM   512
#define BT    128            // block tile (M=N)
#define BK    32             // k chunk per stage
#define NCH   (DIM / BK)     // 16
#define NB    (NROWS / BT)   // 64
#define NBLK  (NB * (NB + 1) / 2)   // 2080 upper-triangle blocks
#define LDS_  36             // padded row stride (floats)

// Scratch (device globals: allocation-free)
__device__ float g_x[NROWS * DIM];   // tf32-rounded weighted features
__device__ float g_sq[NROWS];        // ||x||^2 of ROUNDED x
__device__ float g_ap2[NROWS];
__device__ float g_an2[NROWS];
__device__ int   g_tstride;

static __device__ __forceinline__ float tf32r(float f) {
    uint32_t u;
    asm("cvt.rna.tf32.f32 %0, %1;" : "=r"(u) : "f"(f));
    return __uint_as_float(u);
}
static __device__ __forceinline__ void cp16(uint32_t s, const void* g) {
    asm volatile("cp.async.cg.shared.global [%0], [%1], 16;" :: "r"(s), "l"(g));
}
static __device__ __forceinline__ void mma_tf32(float* d, const uint32_t* a, const uint32_t* b) {
    asm volatile(
        "mma.sync.aligned.m16n8k8.row.col.f32.tf32.tf32.f32 "
        "{%0,%1,%2,%3}, {%4,%5,%6,%7}, {%8,%9}, {%0,%1,%2,%3};\n"
        : "+f"(d[0]), "+f"(d[1]), "+f"(d[2]), "+f"(d[3])
        : "r"(a[0]), "r"(a[1]), "r"(a[2]), "r"(a[3]), "r"(b[0]), "r"(b[1]));
}

// ---------------------------------------------------------------------------
__global__ void detect_kernel(const int* __restrict__ tw) {
    __shared__ int red[32];
    const int t = threadIdx.x;
    int acc = 0;
    for (int i = t; i < NROWS; i += 1024) acc |= tw[2 * i + 1];
    #pragma unroll
    for (int o = 16; o; o >>= 1) acc |= __shfl_down_sync(0xffffffffu, acc, o);
    if ((t & 31) == 0) red[t >> 5] = acc;
    __syncthreads();
    if (t < 32) {
        int v = red[t];
        #pragma unroll
        for (int o = 16; o; o >>= 1) v |= __shfl_down_sync(0xffffffffu, v, o);
        if (t == 0) g_tstride = (v == 0) ? 2 : 1;
    }
}

__global__ void prep_kernel(const float* __restrict__ in, const float* __restrict__ Aw) {
    const int row = blockIdx.x;
    const int t = threadIdx.x;  // 128
    const float4 a = ((const float4*)(in + (size_t)row * DIM))[t];
    const float4 b = ((const float4*)(Aw + (size_t)row * DIM))[t];
    float4 v;
    v.x = tf32r(a.x * b.x); v.y = tf32r(a.y * b.y);
    v.z = tf32r(a.z * b.z); v.w = tf32r(a.w * b.w);
    ((float4*)(g_x + (size_t)row * DIM))[t] = v;
    float s = v.x * v.x + v.y * v.y + v.z * v.z + v.w * v.w;
    #pragma unroll
    for (int o = 16; o; o >>= 1) s += __shfl_down_sync(0xffffffffu, s, o);
    __shared__ float red[4];
    if ((t & 31) == 0) red[t >> 5] = s;
    __syncthreads();
    if (t == 0) {
        g_sq[row]  = red[0] + red[1] + red[2] + red[3];
        g_ap2[row] = 0.0f;
        g_an2[row] = CUDART_INF_F;
    }
}

// ---------------------------------------------------------------------------
// tf32 mma.sync Gram on upper-triangle blocks, fused symmetric hard mining.
// 256 threads = 8 warps (4 in M x 2 in N); warp tile 32x64. 2 CTAs/SM.
// ---------------------------------------------------------------------------
__global__ __launch_bounds__(256, 2) void gram_mma(const int* __restrict__ tw) {
    extern __shared__ float smem[];
    const uint32_t sb = (uint32_t)__cvta_generic_to_shared(smem);
    #define ASo(s) ((s) * (BT * LDS_))
    #define BSo(s) (2 * (BT * LDS_) + (s) * (BT * LDS_))

    const int tid  = threadIdx.x;
    const int lane = tid & 31;
    const int wid  = tid >> 5;
    const int g    = lane >> 2;
    const int c    = lane & 3;
    const int warpM = (wid & 3) * 32;
    const int warpN = (wid >> 2) * 64;
    const int ts = g_tstride;

    // closed-form linear id -> upper triangle (bi <= bj)
    const float fb = (float)blockIdx.x;
    int bi = (int)(64.5f - sqrtf(fmaf(-2.0f, fb, 4160.25f)));
    int rem = blockIdx.x - (bi * (2 * NB - bi + 1)) / 2;
    if (rem < 0) { --bi; rem = blockIdx.x - (bi * (2 * NB - bi + 1)) / 2; }
    else if (rem >= NB - bi) { ++bi; rem = blockIdx.x - (bi * (2 * NB - bi + 1)) / 2; }
    const int bj = bi + rem;
    const int R = bi * BT, C = bj * BT;

    float acc[2][8][4];
    #pragma unroll
    for (int t = 0; t < 2; ++t)
        #pragma unroll
        for (int n = 0; n < 8; ++n)
            #pragma unroll
            for (int e = 0; e < 4; ++e) acc[t][n][e] = 0.f;

    // hoisted load-side addressing: each thread owns 4 (row,ck) granules/side
    const int lrow = tid >> 3;                 // 0..31 (+32 per i)
    const int lck  = (tid & 7) << 4;           // byte offset in 128B row
    const char* gA = (const char*)g_x + ((size_t)(R + lrow) * DIM) * 4 + lck;
    const char* gB = (const char*)g_x + ((size_t)(C + lrow) * DIM) * 4 + lck;
    const uint32_t sA = sb + ((uint32_t)lrow * LDS_) * 4 + lck;
    const uint32_t sB = sb + (uint32_t)(2 * BT * LDS_ * 4) + ((uint32_t)lrow * LDS_) * 4 + lck;
    const size_t gstep = (size_t)32 * DIM * 4;   // 32 rows
    const uint32_t sstep = 32 * LDS_ * 4;

    auto load_stage = [&](int kb, int s) {
        const size_t ko = (size_t)kb * (BK * 4);
        const uint32_t so = (uint32_t)(s * BT * LDS_ * 4);
        #pragma unroll
        for (int i = 0; i < 4; ++i) {
            cp16(sA + so + i * sstep, gA + ko + i * gstep);
            cp16(sB + so + i * sstep, gB + ko + i * gstep);
        }
    };

    load_stage(0, 0);
    asm volatile("cp.async.commit_group;");

    for (int it = 0; it < NCH; ++it) {
        const int s = it & 1;
        if (it + 1 < NCH) load_stage(it + 1, (it + 1) & 1);
        asm volatile("cp.async.commit_group;");
        asm volatile("cp.async.wait_group 1;");
        __syncthreads();

        const float* As = smem + ASo(s);
        const float* Bs = smem + BSo(s);
        #pragma unroll
        for (int kk = 0; kk < 4; ++kk) {
            const int kb = kk * 8;
            uint32_t af[2][4], bf[8][2];
            #pragma unroll
            for (int t = 0; t < 2; ++t) {
                const int r0 = warpM + t * 16 + g;
                af[t][0] = __float_as_uint(As[r0 * LDS_ + kb + c]);
                af[t][1] = __float_as_uint(As[(r0 + 8) * LDS_ + kb + c]);
                af[t][2] = __float_as_uint(As[r0 * LDS_ + kb + c + 4]);
                af[t][3] = __float_as_uint(As[(r0 + 8) * LDS_ + kb + c + 4]);
            }
            #pragma unroll
            for (int n = 0; n < 8; ++n) {
                const int nr = warpN + n * 8 + g;
                bf[n][0] = __float_as_uint(Bs[nr * LDS_ + kb + c]);
                bf[n][1] = __float_as_uint(Bs[nr * LDS_ + kb + c + 4]);
            }
            #pragma unroll
            for (int t = 0; t < 2; ++t)
                #pragma unroll
                for (int n = 0; n < 8; ++n)
                    mma_tf32(acc[t][n], af[t], bf[n]);
        }
        __syncthreads();
    }

    // ---- epilogue: symmetric fused hard mining ----
    float scj[16]; int tcj[16];
    #pragma unroll
    for (int n = 0; n < 8; ++n) {
        const int j0 = C + warpN + n * 8 + 2 * c;
        scj[2*n]   = g_sq[j0];     scj[2*n+1] = g_sq[j0 + 1];
        tcj[2*n]   = tw[ts * j0];  tcj[2*n+1] = tw[ts * (j0 + 1)];
    }
    float sqr4[4]; int tr4[4]; int rowi[4];
    #pragma unroll
    for (int t = 0; t < 2; ++t)
        #pragma unroll
        for (int p = 0; p < 2; ++p) {
            const int ri = R + warpM + t * 16 + p * 8 + g;
            rowi[t*2+p] = ri; sqr4[t*2+p] = g_sq[ri]; tr4[t*2+p] = tw[ts * ri];
        }

    float apr[4], anr[4], apc[16], anc[16];
    #pragma unroll
    for (int i = 0; i < 4; ++i)  { apr[i] = 0.f; anr[i] = CUDART_INF_F; }
    #pragma unroll
    for (int i = 0; i < 16; ++i) { apc[i] = 0.f; anc[i] = CUDART_INF_F; }

    #pragma unroll
    for (int t = 0; t < 2; ++t)
        #pragma unroll
        for (int n = 0; n < 8; ++n)
            #pragma unroll
            for (int p = 0; p < 2; ++p) {
                const int ri = t * 2 + p;
                #pragma unroll
                for (int e = 0; e < 2; ++e) {
                    const int cj = n * 2 + e;
                    const float d2 = fmaf(-2.f, acc[t][n][p * 2 + e], sqr4[ri] + scj[cj]);
                    if (tr4[ri] == tcj[cj]) {
                        apr[ri] = fmaxf(apr[ri], d2);
                        apc[cj] = fmaxf(apc[cj], d2);
                    } else {
                        anr[ri] = fminf(anr[ri], d2);
                        anc[cj] = fminf(anc[cj], d2);
                    }
                }
            }

    #pragma unroll
    for (int i = 0; i < 4; ++i) {
        apr[i] = fmaxf(apr[i], __shfl_xor_sync(0xffffffffu, apr[i], 1));
        apr[i] = fmaxf(apr[i], __shfl_xor_sync(0xffffffffu, apr[i], 2));
        anr[i] = fminf(anr[i], __shfl_xor_sync(0xffffffffu, anr[i], 1));
        anr[i] = fminf(anr[i], __shfl_xor_sync(0xffffffffu, anr[i], 2));
    }
    if (c == 0) {
        #pragma unroll
        for (int i = 0; i < 4; ++i) {
            atomicMax((int*)&g_ap2[rowi[i]], __float_as_int(apr[i]));
            atomicMin((int*)&g_an2[rowi[i]], __float_as_int(anr[i]));
        }
    }
    #pragma unroll
    for (int i = 0; i < 16; ++i) {
        apc[i] = fmaxf(apc[i], __shfl_xor_sync(0xffffffffu, apc[i], 4));
        apc[i] = fmaxf(apc[i], __shfl_xor_sync(0xffffffffu, apc[i], 8));
        apc[i] = fmaxf(apc[i], __shfl_xor_sync(0xffffffffu, apc[i], 16));
        anc[i] = fminf(anc[i], __shfl_xor_sync(0xffffffffu, anc[i], 4));
        anc[i] = fminf(anc[i], __shfl_xor_sync(0xffffffffu, anc[i], 8));
        anc[i] = fminf(anc[i], __shfl_xor_sync(0xffffffffu, anc[i], 16));
    }
    if (g == 0) {
        #pragma unroll
        for (int n = 0; n < 8; ++n)
            #pragma unroll
            for (int e = 0; e < 2; ++e) {
                const int j = C + warpN + n * 8 + 2 * c + e;
                atomicMax((int*)&g_ap2[j], __float_as_int(apc[n * 2 + e]));
                atomicMin((int*)&g_an2[j], __float_as_int(anc[n * 2 + e]));
            }
    }
    #undef ASo
    #undef BSo
}

// ---------------------------------------------------------------------------
__global__ void loss_kernel(float* __restrict__ out) {
    __shared__ float red[32];
    const int t = threadIdx.x;  // 1024
    float s = 0.f;
    #pragma unroll
    for (int h = 0; h < 2; ++h) {
        const int i = t * 8 + h * 4;
        const float4 ap = *(const float4*)&g_ap2[i];
        const float4 an = *(const float4*)&g_an2[i];
        s += fmaxf(sqrtf(fmaxf(ap.x, 1e-12f)) - sqrtf(fmaxf(an.x, 1e-12f)) + 0.5f, 0.f);
        s += fmaxf(sqrtf(fmaxf(ap.y, 1e-12f)) - sqrtf(fmaxf(an.y, 1e-12f)) + 0.5f, 0.f);
        s += fmaxf(sqrtf(fmaxf(ap.z, 1e-12f)) - sqrtf(fmaxf(an.z, 1e-12f)) + 0.5f, 0.f);
        s += fmaxf(sqrtf(fmaxf(ap.w, 1e-12f)) - sqrtf(fmaxf(an.w, 1e-12f)) + 0.5f, 0.f);
    }
    #pragma unroll
    for (int o = 16; o; o >>= 1) s += __shfl_down_sync(0xffffffffu, s, o);
    if ((t & 31) == 0) red[t >> 5] = s;
    __syncthreads();
    if (t < 32) {
        float v = red[t];
        #pragma unroll
        for (int o = 16; o; o >>= 1) v += __shfl_down_sync(0xffffffffu, v, o);
        if (t == 0) out[0] = v * (1.0f / (float)NROWS);
    }
}

// ---------------------------------------------------------------------------
#define SMEM_BYTES (4 * BT * LDS_ * 4)   // 73728 B

extern "C" void kernel_launch(void* const* d_in, const int* in_sizes, int n_in,
                              void* d_out, int out_size) {
    const float* inputs = (const float*)d_in[0];
    const float* A      = (const float*)d_in[1];
    const int*   tw     = (const int*)d_in[2];

    cudaFuncSetAttribute(gram_mma, cudaFuncAttributeMaxDynamicSharedMemorySize, SMEM_BYTES);

    detect_kernel<<<1, 1024>>>(tw);
    prep_kernel<<<NROWS, 128>>>(inputs, A);
    gram_mma<<<NBLK, 256, SMEM_BYTES>>>(tw);
    loss_kernel<<<1, 1024>>>((float*)d_out);
}

// round 7
// speedup vs baseline: 8.9071x; 1.2174x over previous
#include <cuda_runtime.h>
#include <math_constants.h>
#include <cstdint>

#define NROWS 8192
#define DIM   512
#define BT    128            // block tile (M=N)
#define BK    64             // k chunk per stage (bf16)
#define NCH   (DIM / BK)     // 8
#define NB    (NROWS / BT)   // 64
#define NBLK  (NB * (NB + 1) / 2)   // 2080 upper-triangle blocks
#define LDW   36             // padded row stride in b32 units (64 bf16 + 8 pad)
#define STG   (BT * LDW * 4) // 18432 B per stage side
#define SMEM_BYTES (4 * STG) // 73728 B

// Scratch (device globals: allocation-free)
__device__ float    g_x[NROWS * DIM];          // fp32 weighted features (exact)
__device__ uint32_t g_xh[NROWS * DIM / 2];     // bf16x2 packed
__device__ float    g_sq[NROWS];               // ||x||^2 fp32 (exact)
__device__ float    g_sqh[NROWS];              // ||bf16(x)||^2 (consistent w/ gemm)
__device__ unsigned long long g_apP[NROWS];    // packed (d2bits<<32)|argmax col
__device__ unsigned long long g_anP[NROWS];    // packed (d2bits<<32)|argmin col
__device__ float    g_ap2[NROWS];              // exact d2 of selected positive
__device__ float    g_an2[NROWS];              // exact d2 of selected negative
__device__ int      g_tstride;

static __device__ __forceinline__ void cp16(uint32_t s, const void* g) {
    asm volatile("cp.async.cg.shared.global [%0], [%1], 16;" :: "r"(s), "l"(g));
}
static __device__ __forceinline__ uint32_t bf16x2(float lo, float hi) {
    uint32_t r;
    asm("cvt.rn.bf16x2.f32 %0, %1, %2;" : "=r"(r) : "f"(hi), "f"(lo));
    return r;
}
static __device__ __forceinline__ float bf16lo(uint32_t u) { return __uint_as_float(u << 16); }
static __device__ __forceinline__ float bf16hi(uint32_t u) { return __uint_as_float(u & 0xFFFF0000u); }
static __device__ __forceinline__ void mma_bf16(float* d, const uint32_t* a, const uint32_t* b) {
    asm volatile(
        "mma.sync.aligned.m16n8k16.row.col.f32.bf16.bf16.f32 "
        "{%0,%1,%2,%3}, {%4,%5,%6,%7}, {%8,%9}, {%0,%1,%2,%3};\n"
        : "+f"(d[0]), "+f"(d[1]), "+f"(d[2]), "+f"(d[3])
        : "r"(a[0]), "r"(a[1]), "r"(a[2]), "r"(a[3]), "r"(b[0]), "r"(b[1]));
}
static __device__ __forceinline__ unsigned long long packv(float v, int idx) {
    return ((unsigned long long)__float_as_uint(v) << 32) | (unsigned)idx;
}

// ---------------------------------------------------------------------------
__global__ void detect_kernel(const int* __restrict__ tw) {
    __shared__ int red[32];
    const int t = threadIdx.x;
    int acc = 0;
    for (int i = t; i < NROWS; i += 1024) acc |= tw[2 * i + 1];
    #pragma unroll
    for (int o = 16; o; o >>= 1) acc |= __shfl_down_sync(0xffffffffu, acc, o);
    if ((t & 31) == 0) red[t >> 5] = acc;
    __syncthreads();
    if (t < 32) {
        int v = red[t];
        #pragma unroll
        for (int o = 16; o; o >>= 1) v |= __shfl_down_sync(0xffffffffu, v, o);
        if (t == 0) g_tstride = (v == 0) ? 2 : 1;
    }
}

__global__ void prep_kernel(const float* __restrict__ in, const float* __restrict__ Aw) {
    const int row = blockIdx.x;
    const int t = threadIdx.x;  // 128
    const float4 a = ((const float4*)(in + (size_t)row * DIM))[t];
    const float4 b = ((const float4*)(Aw + (size_t)row * DIM))[t];
    float4 v;
    v.x = a.x * b.x; v.y = a.y * b.y; v.z = a.z * b.z; v.w = a.w * b.w;
    ((float4*)(g_x + (size_t)row * DIM))[t] = v;
    const uint32_t p0 = bf16x2(v.x, v.y), p1 = bf16x2(v.z, v.w);
    ((uint2*)(g_xh + (size_t)row * (DIM / 2)))[t] = make_uint2(p0, p1);

    float s  = v.x * v.x + v.y * v.y + v.z * v.z + v.w * v.w;
    const float hx = bf16lo(p0), hy = bf16hi(p0), hz = bf16lo(p1), hw = bf16hi(p1);
    float sh = hx * hx + hy * hy + hz * hz + hw * hw;
    #pragma unroll
    for (int o = 16; o; o >>= 1) {
        s  += __shfl_down_sync(0xffffffffu, s, o);
        sh += __shfl_down_sync(0xffffffffu, sh, o);
    }
    __shared__ float red[4], redh[4];
    if ((t & 31) == 0) { red[t >> 5] = s; redh[t >> 5] = sh; }
    __syncthreads();
    if (t == 0) {
        g_sq[row]  = red[0] + red[1] + red[2] + red[3];
        g_sqh[row] = redh[0] + redh[1] + redh[2] + redh[3];
        g_apP[row] = packv(0.0f, row);            // self-pair fallback (d=0)
        g_anP[row] = 0xFFFFFFFFFFFFFFFFull;
    }
}

// ---------------------------------------------------------------------------
// bf16 mma.sync Gram (selection only) on upper-triangle blocks.
// 256 threads = 8 warps (4 in M x 2 in N); warp tile 32x64.
// ---------------------------------------------------------------------------
__global__ __launch_bounds__(256) void gram_mma(const int* __restrict__ tw) {
    extern __shared__ uint32_t smem[];
    const uint32_t sb = (uint32_t)__cvta_generic_to_shared(smem);

    const int tid  = threadIdx.x;
    const int lane = tid & 31;
    const int wid  = tid >> 5;
    const int g    = lane >> 2;
    const int c    = lane & 3;
    const int warpM = (wid & 3) * 32;
    const int warpN = (wid >> 2) * 64;
    const int ts = g_tstride;

    // closed-form linear id -> upper triangle (bi <= bj)
    const float fb = (float)blockIdx.x;
    int bi = (int)(64.5f - sqrtf(fmaf(-2.0f, fb, 4160.25f)));
    int rem = blockIdx.x - (bi * (2 * NB - bi + 1)) / 2;
    if (rem < 0) { --bi; rem = blockIdx.x - (bi * (2 * NB - bi + 1)) / 2; }
    else if (rem >= NB - bi) { ++bi; rem = blockIdx.x - (bi * (2 * NB - bi + 1)) / 2; }
    const int bj = bi + rem;
    const int R = bi * BT, C = bj * BT;

    float acc[2][8][4];
    #pragma unroll
    for (int t = 0; t < 2; ++t)
        #pragma unroll
        for (int n = 0; n < 8; ++n)
            #pragma unroll
            for (int e = 0; e < 4; ++e) acc[t][n][e] = 0.f;

    // load-side addressing: bf16 rows = 1024 B in gmem, 144 B in smem
    const int lrow = tid >> 3;                 // 0..31 (+32 per i)
    const int lck  = (tid & 7) << 4;           // 0..112 byte offset
    const char* gA = (const char*)g_xh + ((size_t)(R + lrow) * 1024) + lck;
    const char* gB = (const char*)g_xh + ((size_t)(C + lrow) * 1024) + lck;
    const uint32_t sA = sb + (uint32_t)lrow * 144 + lck;
    const uint32_t sB = sb + 2u * STG + (uint32_t)lrow * 144 + lck;
    const size_t gstep = (size_t)32 * 1024;
    const uint32_t sstep = 32 * 144;

    auto load_stage = [&](int kb, int s) {
        const size_t ko = (size_t)kb * 128;        // 64 bf16 = 128 B per chunk
        const uint32_t so = (uint32_t)s * STG;
        #pragma unroll
        for (int i = 0; i < 4; ++i) {
            cp16(sA + so + i * sstep, gA + ko + i * gstep);
            cp16(sB + so + i * sstep, gB + ko + i * gstep);
        }
    };

    load_stage(0, 0);
    asm volatile("cp.async.commit_group;");

    for (int it = 0; it < NCH; ++it) {
        const int s = it & 1;
        if (it + 1 < NCH) load_stage(it + 1, (it + 1) & 1);
        asm volatile("cp.async.commit_group;");
        asm volatile("cp.async.wait_group 1;");
        __syncthreads();

        const uint32_t* As = smem + (size_t)s * (STG / 4);
        const uint32_t* Bs = smem + 2 * (STG / 4) + (size_t)s * (STG / 4);
        #pragma unroll
        for (int kk = 0; kk < 4; ++kk) {          // 4 x k16 steps per k64 chunk
            const int kb = kk * 8;                // b32 offset
            uint32_t af[2][4], bf[8][2];
            #pragma unroll
            for (int t = 0; t < 2; ++t) {
                const int r0 = warpM + t * 16 + g;
                af[t][0] = As[r0 * LDW + kb + c];
                af[t][1] = As[(r0 + 8) * LDW + kb + c];
                af[t][2] = As[r0 * LDW + kb + c + 4];
                af[t][3] = As[(r0 + 8) * LDW + kb + c + 4];
            }
            #pragma unroll
            for (int n = 0; n < 8; ++n) {
                const int nr = warpN + n * 8 + g;
                bf[n][0] = Bs[nr * LDW + kb + c];
                bf[n][1] = Bs[nr * LDW + kb + c + 4];
            }
            #pragma unroll
            for (int t = 0; t < 2; ++t)
                #pragma unroll
                for (int n = 0; n < 8; ++n)
                    mma_bf16(acc[t][n], af[t], bf[n]);
        }
        __syncthreads();
    }

    // ---- epilogue: symmetric hard mining with argmax/argmin tracking ----
    float scj[16]; int tcj[16];
    #pragma unroll
    for (int n = 0; n < 8; ++n) {
        const int j0 = C + warpN + n * 8 + 2 * c;
        scj[2*n]   = g_sqh[j0];    scj[2*n+1] = g_sqh[j0 + 1];
        tcj[2*n]   = tw[ts * j0];  tcj[2*n+1] = tw[ts * (j0 + 1)];
    }
    float sqr4[4]; int tr4[4]; int rowi[4];
    #pragma unroll
    for (int t = 0; t < 2; ++t)
        #pragma unroll
        for (int p = 0; p < 2; ++p) {
            const int ri = R + warpM + t * 16 + p * 8 + g;
            rowi[t*2+p] = ri; sqr4[t*2+p] = g_sqh[ri]; tr4[t*2+p] = tw[ts * ri];
        }

    unsigned long long apr[4], anr[4], apc[16], anc[16];
    #pragma unroll
    for (int i = 0; i < 4; ++i)  { apr[i] = 0ull; anr[i] = 0xFFFFFFFFFFFFFFFFull; }
    #pragma unroll
    for (int i = 0; i < 16; ++i) { apc[i] = 0ull; anc[i] = 0xFFFFFFFFFFFFFFFFull; }

    #pragma unroll
    for (int t = 0; t < 2; ++t)
        #pragma unroll
        for (int n = 0; n < 8; ++n)
            #pragma unroll
            for (int p = 0; p < 2; ++p) {
                const int ri = t * 2 + p;
                #pragma unroll
                for (int e = 0; e < 2; ++e) {
                    const int cj = n * 2 + e;
                    const int jg = C + warpN + n * 8 + 2 * c + e;
                    const float d2 = fmaxf(fmaf(-2.f, acc[t][n][p * 2 + e], sqr4[ri] + scj[cj]), 0.f);
                    if (tr4[ri] == tcj[cj]) {
                        const unsigned long long pr = packv(d2, jg);
                        const unsigned long long pc = packv(d2, rowi[ri]);
                        if (pr > apr[ri]) apr[ri] = pr;
                        if (pc > apc[cj]) apc[cj] = pc;
                    } else {
                        const unsigned long long pr = packv(d2, jg);
                        const unsigned long long pc = packv(d2, rowi[ri]);
                        if (pr < anr[ri]) anr[ri] = pr;
                        if (pc < anc[cj]) anc[cj] = pc;
                    }
                }
            }

    // row-side: reduce across c lanes (xor 1,2)
    #pragma unroll
    for (int i = 0; i < 4; ++i) {
        #pragma unroll
        for (int m = 1; m <= 2; m <<= 1) {
            unsigned long long o;
            o = __shfl_xor_sync(0xffffffffu, apr[i], m); if (o > apr[i]) apr[i] = o;
            o = __shfl_xor_sync(0xffffffffu, anr[i], m); if (o < anr[i]) anr[i] = o;
        }
    }
    if (c == 0) {
        #pragma unroll
        for (int i = 0; i < 4; ++i) {
            atomicMax(&g_apP[rowi[i]], apr[i]);
            atomicMin(&g_anP[rowi[i]], anr[i]);
        }
    }
    // col-side: reduce across g lanes (xor 4,8,16)
    #pragma unroll
    for (int i = 0; i < 16; ++i) {
        #pragma unroll
        for (int m = 4; m <= 16; m <<= 1) {
            unsigned long long o;
            o = __shfl_xor_sync(0xffffffffu, apc[i], m); if (o > apc[i]) apc[i] = o;
            o = __shfl_xor_sync(0xffffffffu, anc[i], m); if (o < anc[i]) anc[i] = o;
        }
    }
    if (g == 0) {
        #pragma unroll
        for (int n = 0; n < 8; ++n)
            #pragma unroll
            for (int e = 0; e < 2; ++e) {
                const int j = C + warpN + n * 8 + 2 * c + e;
                atomicMax(&g_apP[j], apc[n * 2 + e]);
                atomicMin(&g_anP[j], anc[n * 2 + e]);
            }
    }
}

// ---------------------------------------------------------------------------
// Refine: exact fp32 dist^2 for the selected (argmax, argmin) pairs.
// One warp per row; two 512-dots per warp.
// ---------------------------------------------------------------------------
__global__ __launch_bounds__(256) void refine_kernel() {
    const int wid  = threadIdx.x >> 5;
    const int lane = threadIdx.x & 31;
    const int row  = blockIdx.x * 8 + wid;

    const int jp = (int)(unsigned)(g_apP[row] & 0xFFFFFFFFull);
    const int jn = (int)(unsigned)(g_anP[row] & 0xFFFFFFFFull);

    const float4* xi = (const float4*)(g_x + (size_t)row * DIM);
    const float4* xp = (const float4*)(g_x + (size_t)jp * DIM);
    const float4* xn = (const float4*)(g_x + (size_t)jn * DIM);
    float dp = 0.f, dn = 0.f;
    #pragma unroll
    for (int q = 0; q < 4; ++q) {
        const float4 a = xi[q * 32 + lane];
        const float4 b = xp[q * 32 + lane];
        const float4 d = xn[q * 32 + lane];
        dp = fmaf(a.x, b.x, fmaf(a.y, b.y, fmaf(a.z, b.z, fmaf(a.w, b.w, dp))));
        dn = fmaf(a.x, d.x, fmaf(a.y, d.y, fmaf(a.z, d.z, fmaf(a.w, d.w, dn))));
    }
    #pragma unroll
    for (int o = 16; o; o >>= 1) {
        dp += __shfl_down_sync(0xffffffffu, dp, o);
        dn += __shfl_down_sync(0xffffffffu, dn, o);
    }
    if (lane == 0) {
        g_ap2[row] = fmaf(-2.f, dp, g_sq[row] + g_sq[jp]);
        g_an2[row] = fmaf(-2.f, dn, g_sq[row] + g_sq[jn]);
    }
}

// ---------------------------------------------------------------------------
__global__ void loss_kernel(float* __restrict__ out) {
    __shared__ float red[32];
    const int t = threadIdx.x;  // 1024
    float s = 0.f;
    #pragma unroll
    for (int h = 0; h < 2; ++h) {
        const int i = t * 8 + h * 4;
        const float4 ap = *(const float4*)&g_ap2[i];
        const float4 an = *(const float4*)&g_an2[i];
        s += fmaxf(sqrtf(fmaxf(ap.x, 1e-12f)) - sqrtf(fmaxf(an.x, 1e-12f)) + 0.5f, 0.f);
        s += fmaxf(sqrtf(fmaxf(ap.y, 1e-12f)) - sqrtf(fmaxf(an.y, 1e-12f)) + 0.5f, 0.f);
        s += fmaxf(sqrtf(fmaxf(ap.z, 1e-12f)) - sqrtf(fmaxf(an.z, 1e-12f)) + 0.5f, 0.f);
        s += fmaxf(sqrtf(fmaxf(ap.w, 1e-12f)) - sqrtf(fmaxf(an.w, 1e-12f)) + 0.5f, 0.f);
    }
    #pragma unroll
    for (int o = 16; o; o >>= 1) s += __shfl_down_sync(0xffffffffu, s, o);
    if ((t & 31) == 0) red[t >> 5] = s;
    __syncthreads();
    if (t < 32) {
        float v = red[t];
        #pragma unroll
        for (int o = 16; o; o >>= 1) v += __shfl_down_sync(0xffffffffu, v, o);
        if (t == 0) out[0] = v * (1.0f / (float)NROWS);
    }
}

// ---------------------------------------------------------------------------
extern "C" void kernel_launch(void* const* d_in, const int* in_sizes, int n_in,
                              void* d_out, int out_size) {
    const float* inputs = (const float*)d_in[0];
    const float* A      = (const float*)d_in[1];
    const int*   tw     = (const int*)d_in[2];

    cudaFuncSetAttribute(gram_mma, cudaFuncAttributeMaxDynamicSharedMemorySize, SMEM_BYTES);

    detect_kernel<<<1, 1024>>>(tw);
    prep_kernel<<<NROWS, 128>>>(inputs, A);
    gram_mma<<<NBLK, 256, SMEM_BYTES>>>(tw);
    refine_kernel<<<NROWS / 8, 256>>>();
    loss_kernel<<<1, 1024>>>((float*)d_out);
}

// round 11
// speedup vs baseline: 9.5388x; 1.0709x over previous
#include <cuda_runtime.h>
#include <cuda_fp16.h>
#include <math_constants.h>
#include <cstdint>

#define NROWS 8192
#define DIM   512
#define BT    128            // block tile (M=N)
#define NCH   4              // k chunks of 128 fp8
#define NB    (NROWS / BT)   // 64
#define NBLK  (NB * (NB + 1) / 2)   // 2080 upper-triangle blocks
#define LDW   36             // padded row stride in b32 units (32 data + 4 pad)
#define STG   (BT * LDW * 4) // 18432 B per stage side
#define SMEM_BYTES (4 * STG) // 73728 B
typedef unsigned long long ull;

// Scratch (device globals: allocation-free)
__device__ float    g_x[NROWS * DIM];          // fp32 weighted features (exact)
__device__ uint32_t g_x8[NROWS * DIM / 4];     // e4m3 x4 packed
__device__ float    g_sq[NROWS];               // ||x||^2 fp32 (exact)
__device__ float    g_sqq[NROWS];              // ||e4m3(x)||^2 (consistent geometry)
__device__ ull      g_negC[(size_t)NROWS * NB]; // per-(row, colblock) min-neg cand
__device__ ull      g_posC[(size_t)NROWS * NB]; // per-(row, colblock) max-pos cand
__device__ float    g_ap2[NROWS];              // exact d2 of refined positive
__device__ float    g_an2[NROWS];              // exact d2 of refined negative
__device__ int      g_tstride;

static __device__ __forceinline__ void cp16(uint32_t s, const void* g) {
    asm volatile("cp.async.cg.shared.global [%0], [%1], 16;" :: "r"(s), "l"(g));
}
static __device__ __forceinline__ uint32_t e4m3x4(float v0, float v1, float v2, float v3) {
    uint16_t lo, hi;
    asm("cvt.rn.satfinite.e4m3x2.f32 %0, %1, %2;" : "=h"(lo) : "f"(v1), "f"(v0));
    asm("cvt.rn.satfinite.e4m3x2.f32 %0, %1, %2;" : "=h"(hi) : "f"(v3), "f"(v2));
    return (uint32_t)lo | ((uint32_t)hi << 16);
}
static __device__ __forceinline__ float2 dq2(uint16_t u) {
    uint32_t h2;
    asm("cvt.rn.f16x2.e4m3x2 %0, %1;" : "=r"(h2) : "h"(u));
    const __half2 h = *reinterpret_cast<const __half2*>(&h2);
    return __half22float2(h);
}
static __device__ __forceinline__ void mma_fp8(float* d, const uint32_t* a, const uint32_t* b) {
    asm volatile(
        "mma.sync.aligned.m16n8k32.row.col.f32.e4m3.e4m3.f32 "
        "{%0,%1,%2,%3}, {%4,%5,%6,%7}, {%8,%9}, {%0,%1,%2,%3};\n"
        : "+f"(d[0]), "+f"(d[1]), "+f"(d[2]), "+f"(d[3])
        : "r"(a[0]), "r"(a[1]), "r"(a[2]), "r"(a[3]), "r"(b[0]), "r"(b[1]));
}
static __device__ __forceinline__ ull packv(float v, int idx) {
    return ((ull)__float_as_uint(v) << 32) | (unsigned)idx;
}

// ---------------------------------------------------------------------------
__global__ void detect_kernel(const int* __restrict__ tw) {
    __shared__ int red[32];
    const int t = threadIdx.x;
    int acc = 0;
    for (int i = t; i < NROWS; i += 1024) acc |= tw[2 * i + 1];
    #pragma unroll
    for (int o = 16; o; o >>= 1) acc |= __shfl_down_sync(0xffffffffu, acc, o);
    if ((t & 31) == 0) red[t >> 5] = acc;
    __syncthreads();
    if (t < 32) {
        int v = red[t];
        #pragma unroll
        for (int o = 16; o; o >>= 1) v |= __shfl_down_sync(0xffffffffu, v, o);
        if (t == 0) g_tstride = (v == 0) ? 2 : 1;
    }
}

__global__ void prep_kernel(const float* __restrict__ in, const float* __restrict__ Aw) {
    const int row = blockIdx.x;
    const int t = threadIdx.x;  // 128
    const float4 a = ((const float4*)(in + (size_t)row * DIM))[t];
    const float4 b = ((const float4*)(Aw + (size_t)row * DIM))[t];
    float4 v;
    v.x = a.x * b.x; v.y = a.y * b.y; v.z = a.z * b.z; v.w = a.w * b.w;
    ((float4*)(g_x + (size_t)row * DIM))[t] = v;

    const uint32_t p = e4m3x4(v.x, v.y, v.z, v.w);
    g_x8[(size_t)row * (DIM / 4) + t] = p;

    float s = v.x * v.x + v.y * v.y + v.z * v.z + v.w * v.w;
    const float2 q0 = dq2((uint16_t)(p & 0xFFFFu));
    const float2 q1 = dq2((uint16_t)(p >> 16));
    float sq8 = q0.x * q0.x + q0.y * q0.y + q1.x * q1.x + q1.y * q1.y;
    #pragma unroll
    for (int o = 16; o; o >>= 1) {
        s   += __shfl_down_sync(0xffffffffu, s, o);
        sq8 += __shfl_down_sync(0xffffffffu, sq8, o);
    }
    __shared__ float red[4], redq[4];
    if ((t & 31) == 0) { red[t >> 5] = s; redq[t >> 5] = sq8; }
    __syncthreads();
    if (t == 0) {
        g_sq[row]  = red[0] + red[1] + red[2] + red[3];
        g_sqq[row] = redq[0] + redq[1] + redq[2] + redq[3];
    }
}

// ---------------------------------------------------------------------------
// fp8 e4m3 mma.sync Gram (selection only) on upper-triangle blocks.
// Per-block candidates written to g_negC/g_posC (no atomics).
// ---------------------------------------------------------------------------
__global__ __launch_bounds__(256, 2) void gram_mma(const int* __restrict__ tw) {
    extern __shared__ uint32_t smem[];
    const uint32_t sb = (uint32_t)__cvta_generic_to_shared(smem);

    const int tid  = threadIdx.x;
    const int lane = tid & 31;
    const int wid  = tid >> 5;
    const int g    = lane >> 2;
    const int c    = lane & 3;
    const int warpM = (wid & 3) * 32;
    const int warpN = (wid >> 2) * 64;
    const int ts = g_tstride;

    // closed-form linear id -> upper triangle (bi <= bj)
    const float fb = (float)blockIdx.x;
    int bi = (int)(64.5f - sqrtf(fmaf(-2.0f, fb, 4160.25f)));
    int rem = blockIdx.x - (bi * (2 * NB - bi + 1)) / 2;
    if (rem < 0) { --bi; rem = blockIdx.x - (bi * (2 * NB - bi + 1)) / 2; }
    else if (rem >= NB - bi) { ++bi; rem = blockIdx.x - (bi * (2 * NB - bi + 1)) / 2; }
    const int bj = bi + rem;
    const int R = bi * BT, C = bj * BT;

    float acc[2][8][4];
    #pragma unroll
    for (int t = 0; t < 2; ++t)
        #pragma unroll
        for (int n = 0; n < 8; ++n)
            #pragma unroll
            for (int e = 0; e < 4; ++e) acc[t][n][e] = 0.f;

    const int lrow = tid >> 3;
    const int lck  = (tid & 7) << 4;
    const char* gA = (const char*)g_x8 + ((size_t)(R + lrow) * 512) + lck;
    const char* gB = (const char*)g_x8 + ((size_t)(C + lrow) * 512) + lck;
    const uint32_t sA = sb + (uint32_t)lrow * 144 + lck;
    const uint32_t sB = sb + 2u * STG + (uint32_t)lrow * 144 + lck;
    const size_t gstep = (size_t)32 * 512;
    const uint32_t sstep = 32 * 144;

    auto load_stage = [&](int kb, int s) {
        const size_t ko = (size_t)kb * 128;
        const uint32_t so = (uint32_t)s * STG;
        #pragma unroll
        for (int i = 0; i < 4; ++i) {
            cp16(sA + so + i * sstep, gA + ko + i * gstep);
            cp16(sB + so + i * sstep, gB + ko + i * gstep);
        }
    };

    load_stage(0, 0);
    asm volatile("cp.async.commit_group;");

    for (int it = 0; it < NCH; ++it) {
        const int s = it & 1;
        if (it + 1 < NCH) load_stage(it + 1, (it + 1) & 1);
        asm volatile("cp.async.commit_group;");
        asm volatile("cp.async.wait_group 1;");
        __syncthreads();

        const uint32_t* As = smem + (size_t)s * (STG / 4);
        const uint32_t* Bs = smem + 2 * (STG / 4) + (size_t)s * (STG / 4);
        #pragma unroll
        for (int kk = 0; kk < 4; ++kk) {
            const int kb = kk * 8;
            uint32_t af[2][4], bf[8][2];
            #pragma unroll
            for (int t = 0; t < 2; ++t) {
                const int r0 = warpM + t * 16 + g;
                af[t][0] = As[r0 * LDW + kb + c];
                af[t][1] = As[(r0 + 8) * LDW + kb + c];
                af[t][2] = As[r0 * LDW + kb + c + 4];
                af[t][3] = As[(r0 + 8) * LDW + kb + c + 4];
            }
            #pragma unroll
            for (int n = 0; n < 8; ++n) {
                const int nr = warpN + n * 8 + g;
                bf[n][0] = Bs[nr * LDW + kb + c];
                bf[n][1] = Bs[nr * LDW + kb + c + 4];
            }
            #pragma unroll
            for (int t = 0; t < 2; ++t)
                #pragma unroll
                for (int n = 0; n < 8; ++n)
                    mma_fp8(acc[t][n], af[t], bf[n]);
        }
        __syncthreads();
    }

    // ---- epilogue: symmetric hard mining, per-block candidate output ----
    float scj[16]; int tcj[16];
    #pragma unroll
    for (int n = 0; n < 8; ++n) {
        const int j0 = C + warpN + n * 8 + 2 * c;
        scj[2*n]   = g_sqq[j0];    scj[2*n+1] = g_sqq[j0 + 1];
        tcj[2*n]   = tw[ts * j0];  tcj[2*n+1] = tw[ts * (j0 + 1)];
    }
    float sqr4[4]; int tr4[4]; int rowi[4];
    #pragma unroll
    for (int t = 0; t < 2; ++t)
        #pragma unroll
        for (int p = 0; p < 2; ++p) {
            const int ri = R + warpM + t * 16 + p * 8 + g;
            rowi[t*2+p] = ri; sqr4[t*2+p] = g_sqq[ri]; tr4[t*2+p] = tw[ts * ri];
        }

    ull apr[4], anr[4], apc[16], anc[16];
    #pragma unroll
    for (int i = 0; i < 4; ++i)  { apr[i] = packv(0.0f, rowi[i]); anr[i] = 0xFFFFFFFFFFFFFFFFull; }
    #pragma unroll
    for (int n = 0; n < 8; ++n)
        #pragma unroll
        for (int e = 0; e < 2; ++e) {
            const int cj = n * 2 + e;
            apc[cj] = packv(0.0f, C + warpN + n * 8 + 2 * c + e);
            anc[cj] = 0xFFFFFFFFFFFFFFFFull;
        }

    #pragma unroll
    for (int t = 0; t < 2; ++t)
        #pragma unroll
        for (int n = 0; n < 8; ++n)
            #pragma unroll
            for (int p = 0; p < 2; ++p) {
                const int ri = t * 2 + p;
                #pragma unroll
                for (int e = 0; e < 2; ++e) {
                    const int cj = n * 2 + e;
                    const int jg = C + warpN + n * 8 + 2 * c + e;
                    const float d2 = fmaxf(fmaf(-2.f, acc[t][n][p * 2 + e], sqr4[ri] + scj[cj]), 0.f);
                    const ull pr = packv(d2, jg);
                    const ull pc = packv(d2, rowi[ri]);
                    if (tr4[ri] == tcj[cj]) {
                        if (pr > apr[ri]) apr[ri] = pr;
                        if (pc > apc[cj]) apc[cj] = pc;
                    } else {
                        if (pr < anr[ri]) anr[ri] = pr;
                        if (pc < anc[cj]) anc[cj] = pc;
                    }
                }
            }

    // warp-level reductions
    #pragma unroll
    for (int i = 0; i < 4; ++i) {
        #pragma unroll
        for (int m = 1; m <= 2; m <<= 1) {
            ull o;
            o = __shfl_xor_sync(0xffffffffu, apr[i], m); if (o > apr[i]) apr[i] = o;
            o = __shfl_xor_sync(0xffffffffu, anr[i], m); if (o < anr[i]) anr[i] = o;
        }
    }
    #pragma unroll
    for (int i = 0; i < 16; ++i) {
        #pragma unroll
        for (int m = 4; m <= 16; m <<= 1) {
            ull o;
            o = __shfl_xor_sync(0xffffffffu, apc[i], m); if (o > apc[i]) apc[i] = o;
            o = __shfl_xor_sync(0xffffffffu, anc[i], m); if (o < anc[i]) anc[i] = o;
        }
    }

    // block-level combine in (reused) smem, then plain global stores
    ull* s_rap = (ull*)smem;            // [128][2]
    ull* s_ran = s_rap + 256;           // [128][2]
    ull* s_cap = s_ran + 256;           // [128][4]
    ull* s_can = s_cap + 512;           // [128][4]
    const int colgrp = wid >> 2;
    const int mgrp   = wid & 3;

    if (c == 0) {
        #pragma unroll
        for (int i = 0; i < 4; ++i) {
            const int lr = warpM + (i >> 1) * 16 + (i & 1) * 8 + g;
            s_rap[lr * 2 + colgrp] = apr[i];
            s_ran[lr * 2 + colgrp] = anr[i];
        }
    }
    if (g == 0) {
        #pragma unroll
        for (int n = 0; n < 8; ++n)
            #pragma unroll
            for (int e = 0; e < 2; ++e) {
                const int lc = warpN + n * 8 + 2 * c + e;
                s_cap[lc * 4 + mgrp] = apc[n * 2 + e];
                s_can[lc * 4 + mgrp] = anc[n * 2 + e];
            }
    }
    __syncthreads();
    if (tid < 128) {
        ull a0 = s_rap[tid * 2], a1 = s_rap[tid * 2 + 1];
        ull b0 = s_ran[tid * 2], b1 = s_ran[tid * 2 + 1];
        g_posC[(size_t)(R + tid) * NB + bj] = a0 > a1 ? a0 : a1;
        g_negC[(size_t)(R + tid) * NB + bj] = b0 < b1 ? b0 : b1;
        if (bi != bj) {
            ull ca = s_cap[tid * 4], cn = s_can[tid * 4];
            #pragma unroll
            for (int q = 1; q < 4; ++q) {
                const ull ua = s_cap[tid * 4 + q], un = s_can[tid * 4 + q];
                if (ua > ca) ca = ua;
                if (un < cn) cn = un;
            }
            g_posC[(size_t)(C + tid) * NB + bi] = ca;
            g_negC[(size_t)(C + tid) * NB + bi] = cn;
        }
    }
}

// ---------------------------------------------------------------------------
// Refine: top-4 negative / top-2 positive block candidates, exact fp32 d2.
// One warp per row.
// ---------------------------------------------------------------------------
__global__ __launch_bounds__(256) void refine_kernel() {
    const int wid  = threadIdx.x >> 5;
    const int lane = threadIdx.x & 31;
    const int row  = blockIdx.x * 8 + wid;

    const ull* neg = &g_negC[(size_t)row * NB];
    const ull* pos = &g_posC[(size_t)row * NB];
    const float sqi = g_sq[row];
    const float4* xi = (const float4*)(g_x + (size_t)row * DIM);
    float4 xv[4];
    #pragma unroll
    for (int q = 0; q < 4; ++q) xv[q] = xi[q * 32 + lane];

    auto exact_d2 = [&](int j) -> float {
        const float4* xj = (const float4*)(g_x + (size_t)j * DIM);
        float dot = 0.f;
        #pragma unroll
        for (int q = 0; q < 4; ++q) {
            const float4 b = xj[q * 32 + lane];
            dot = fmaf(xv[q].x, b.x, fmaf(xv[q].y, b.y, fmaf(xv[q].z, b.z, fmaf(xv[q].w, b.w, dot))));
        }
        #pragma unroll
        for (int o = 16; o; o >>= 1) dot += __shfl_xor_sync(0xffffffffu, dot, o);
        return fmaf(-2.f, dot, sqi + g_sq[j]);
    };

    // negatives: top-4 smallest packed candidates, exact min
    ull c0 = neg[lane], c1 = neg[lane + 32];
    float an = CUDART_INF_F;
    #pragma unroll
    for (int k = 0; k < 4; ++k) {
        ull m = c0 < c1 ? c0 : c1;
        #pragma unroll
        for (int o = 16; o; o >>= 1) {
            const ull v = __shfl_xor_sync(0xffffffffu, m, o);
            if (v < m) m = v;
        }
        if (c0 == m) c0 = 0xFFFFFFFFFFFFFFFFull;
        else if (c1 == m) c1 = 0xFFFFFFFFFFFFFFFFull;
        if (m != 0xFFFFFFFFFFFFFFFFull) {
            const int j = (int)((unsigned)m & 8191u);
            an = fminf(an, exact_d2(j));
        }
    }

    // positives: top-2 largest packed candidates, exact max
    ull p0 = pos[lane], p1 = pos[lane + 32];
    float ap = 0.f;
    #pragma unroll
    for (int k = 0; k < 2; ++k) {
        ull m = p0 > p1 ? p0 : p1;
        #pragma unroll
        for (int o = 16; o; o >>= 1) {
            const ull v = __shfl_xor_sync(0xffffffffu, m, o);
            if (v > m) m = v;
        }
        if (p0 == m) p0 = 0ull;
        else if (p1 == m) p1 = 0ull;
        const int j = (int)((unsigned)m & 8191u);
        ap = fmaxf(ap, exact_d2(j));
    }

    if (lane == 0) {
        g_an2[row] = an;
        g_ap2[row] = ap;
    }
}

// ---------------------------------------------------------------------------
__global__ void loss_kernel(float* __restrict__ out) {
    __shared__ float red[32];
    const int t = threadIdx.x;  // 1024
    float s = 0.f;
    #pragma unroll
    for (int h = 0; h < 2; ++h) {
        const int i = t * 8 + h * 4;
        const float4 ap = *(const float4*)&g_ap2[i];
        const float4 an = *(const float4*)&g_an2[i];
        s += fmaxf(sqrtf(fmaxf(ap.x, 1e-12f)) - sqrtf(fmaxf(an.x, 1e-12f)) + 0.5f, 0.f);
        s += fmaxf(sqrtf(fmaxf(ap.y, 1e-12f)) - sqrtf(fmaxf(an.y, 1e-12f)) + 0.5f, 0.f);
        s += fmaxf(sqrtf(fmaxf(ap.z, 1e-12f)) - sqrtf(fmaxf(an.z, 1e-12f)) + 0.5f, 0.f);
        s += fmaxf(sqrtf(fmaxf(ap.w, 1e-12f)) - sqrtf(fmaxf(an.w, 1e-12f)) + 0.5f, 0.f);
    }
    #pragma unroll
    for (int o = 16; o; o >>= 1) s += __shfl_down_sync(0xffffffffu, s, o);
    if ((t & 31) == 0) red[t >> 5] = s;
    __syncthreads();
    if (t < 32) {
        float v = red[t];
        #pragma unroll
        for (int o = 16; o; o >>= 1) v += __shfl_down_sync(0xffffffffu, v, o);
        if (t == 0) out[0] = v * (1.0f / (float)NROWS);
    }
}

// ---------------------------------------------------------------------------
extern "C" void kernel_launch(void* const* d_in, const int* in_sizes, int n_in,
                              void* d_out, int out_size) {
    const float* inputs = (const float*)d_in[0];
    const float* A      = (const float*)d_in[1];
    const int*   tw     = (const int*)d_in[2];

    cudaFuncSetAttribute(gram_mma, cudaFuncAttributeMaxDynamicSharedMemorySize, SMEM_BYTES);

    detect_kernel<<<1, 1024>>>(tw);
    prep_kernel<<<NROWS, 128>>>(inputs, A);
    gram_mma<<<NBLK, 256, SMEM_BYTES>>>(tw);
    refine_kernel<<<NROWS / 8, 256>>>();
    loss_kernel<<<1, 1024>>>((float*)d_out);
}

// round 12
// speedup vs baseline: 9.6352x; 1.0101x over previous
#include <cuda_runtime.h>
#include <cuda_fp16.h>
#include <math_constants.h>
#include <cstdint>

#define NROWS 8192
#define DIM   512
#define BT    128            // block tile (M=N)
#define NCH   4              // k chunks of 128 fp8
#define NB    (NROWS / BT)   // 64
#define NBLK  (NB * (NB + 1) / 2)   // 2080 upper-triangle blocks
#define LDW   36             // padded row stride in b32 units (32 data + 4 pad)
#define STG   (BT * LDW * 4) // 18432 B per stage side
#define SMEM_BYTES (4 * STG) // 73728 B
typedef unsigned long long ull;

// Scratch (device globals: allocation-free)
__device__ float    g_x[NROWS * DIM];          // fp32 weighted features (exact)
__device__ uint32_t g_x8[NROWS * DIM / 4];     // e4m3 x4 packed
__device__ float    g_sq[NROWS];               // ||x||^2 fp32 (exact)
__device__ float    g_sqq[NROWS];              // ||e4m3(x)||^2 (consistent geometry)
__device__ ull      g_negC[(size_t)NROWS * NB]; // per-(row, colblock) min-neg cand
__device__ ull      g_posC[(size_t)NROWS * NB]; // per-(row, colblock) max-pos cand
__device__ float    g_ap2[NROWS];              // exact d2 of refined positive
__device__ float    g_an2[NROWS];              // exact d2 of refined negative
__device__ int      g_tstride;

static __device__ __forceinline__ void cp16(uint32_t s, const void* g) {
    asm volatile("cp.async.cg.shared.global [%0], [%1], 16;" :: "r"(s), "l"(g));
}
static __device__ __forceinline__ uint32_t e4m3x4(float v0, float v1, float v2, float v3) {
    uint16_t lo, hi;
    asm("cvt.rn.satfinite.e4m3x2.f32 %0, %1, %2;" : "=h"(lo) : "f"(v1), "f"(v0));
    asm("cvt.rn.satfinite.e4m3x2.f32 %0, %1, %2;" : "=h"(hi) : "f"(v3), "f"(v2));
    return (uint32_t)lo | ((uint32_t)hi << 16);
}
static __device__ __forceinline__ float2 dq2(uint16_t u) {
    uint32_t h2;
    asm("cvt.rn.f16x2.e4m3x2 %0, %1;" : "=r"(h2) : "h"(u));
    const __half2 h = *reinterpret_cast<const __half2*>(&h2);
    return __half22float2(h);
}
static __device__ __forceinline__ void mma_fp8(float* d, const uint32_t* a, const uint32_t* b) {
    asm volatile(
        "mma.sync.aligned.m16n8k32.row.col.f32.e4m3.e4m3.f32 "
        "{%0,%1,%2,%3}, {%4,%5,%6,%7}, {%8,%9}, {%0,%1,%2,%3};\n"
        : "+f"(d[0]), "+f"(d[1]), "+f"(d[2]), "+f"(d[3])
        : "r"(a[0]), "r"(a[1]), "r"(a[2]), "r"(a[3]), "r"(b[0]), "r"(b[1]));
}
static __device__ __forceinline__ ull packv(float v, int idx) {
    return ((ull)__float_as_uint(v) << 32) | (unsigned)idx;
}

// ---------------------------------------------------------------------------
__global__ void detect_kernel(const int* __restrict__ tw) {
    __shared__ int red[32];
    const int t = threadIdx.x;
    int acc = 0;
    for (int i = t; i < NROWS; i += 1024) acc |= tw[2 * i + 1];
    #pragma unroll
    for (int o = 16; o; o >>= 1) acc |= __shfl_down_sync(0xffffffffu, acc, o);
    if ((t & 31) == 0) red[t >> 5] = acc;
    __syncthreads();
    if (t < 32) {
        int v = red[t];
        #pragma unroll
        for (int o = 16; o; o >>= 1) v |= __shfl_down_sync(0xffffffffu, v, o);
        if (t == 0) g_tstride = (v == 0) ? 2 : 1;
    }
}

__global__ void prep_kernel(const float* __restrict__ in, const float* __restrict__ Aw) {
    const int row = blockIdx.x;
    const int t = threadIdx.x;  // 128
    const float4 a = ((const float4*)(in + (size_t)row * DIM))[t];
    const float4 b = ((const float4*)(Aw + (size_t)row * DIM))[t];
    float4 v;
    v.x = a.x * b.x; v.y = a.y * b.y; v.z = a.z * b.z; v.w = a.w * b.w;
    ((float4*)(g_x + (size_t)row * DIM))[t] = v;

    const uint32_t p = e4m3x4(v.x, v.y, v.z, v.w);
    g_x8[(size_t)row * (DIM / 4) + t] = p;

    float s = v.x * v.x + v.y * v.y + v.z * v.z + v.w * v.w;
    const float2 q0 = dq2((uint16_t)(p & 0xFFFFu));
    const float2 q1 = dq2((uint16_t)(p >> 16));
    float sq8 = q0.x * q0.x + q0.y * q0.y + q1.x * q1.x + q1.y * q1.y;
    #pragma unroll
    for (int o = 16; o; o >>= 1) {
        s   += __shfl_down_sync(0xffffffffu, s, o);
        sq8 += __shfl_down_sync(0xffffffffu, sq8, o);
    }
    __shared__ float red[4], redq[4];
    if ((t & 31) == 0) { red[t >> 5] = s; redq[t >> 5] = sq8; }
    __syncthreads();
    if (t == 0) {
        g_sq[row]  = red[0] + red[1] + red[2] + red[3];
        g_sqq[row] = redq[0] + redq[1] + redq[2] + redq[3];
    }
}

// ---------------------------------------------------------------------------
// fp8 e4m3 mma.sync Gram (selection only) on upper-triangle blocks.
// Per-block candidates written to g_negC/g_posC (no atomics).
// ---------------------------------------------------------------------------
__global__ __launch_bounds__(256, 2) void gram_mma(const int* __restrict__ tw) {
    extern __shared__ uint32_t smem[];
    const uint32_t sb = (uint32_t)__cvta_generic_to_shared(smem);

    const int tid  = threadIdx.x;
    const int lane = tid & 31;
    const int wid  = tid >> 5;
    const int g    = lane >> 2;
    const int c    = lane & 3;
    const int warpM = (wid & 3) * 32;
    const int warpN = (wid >> 2) * 64;
    const int ts = g_tstride;

    // closed-form linear id -> upper triangle (bi <= bj)
    const float fb = (float)blockIdx.x;
    int bi = (int)(64.5f - sqrtf(fmaf(-2.0f, fb, 4160.25f)));
    int rem = blockIdx.x - (bi * (2 * NB - bi + 1)) / 2;
    if (rem < 0) { --bi; rem = blockIdx.x - (bi * (2 * NB - bi + 1)) / 2; }
    else if (rem >= NB - bi) { ++bi; rem = blockIdx.x - (bi * (2 * NB - bi + 1)) / 2; }
    const int bj = bi + rem;
    const int R = bi * BT, C = bj * BT;

    float acc[2][8][4];
    #pragma unroll
    for (int t = 0; t < 2; ++t)
        #pragma unroll
        for (int n = 0; n < 8; ++n)
            #pragma unroll
            for (int e = 0; e < 4; ++e) acc[t][n][e] = 0.f;

    const int lrow = tid >> 3;
    const int lck  = (tid & 7) << 4;
    const char* gA = (const char*)g_x8 + ((size_t)(R + lrow) * 512) + lck;
    const char* gB = (const char*)g_x8 + ((size_t)(C + lrow) * 512) + lck;
    const uint32_t sA = sb + (uint32_t)lrow * 144 + lck;
    const uint32_t sB = sb + 2u * STG + (uint32_t)lrow * 144 + lck;
    const size_t gstep = (size_t)32 * 512;
    const uint32_t sstep = 32 * 144;

    auto load_stage = [&](int kb, int s) {
        const size_t ko = (size_t)kb * 128;
        const uint32_t so = (uint32_t)s * STG;
        #pragma unroll
        for (int i = 0; i < 4; ++i) {
            cp16(sA + so + i * sstep, gA + ko + i * gstep);
            cp16(sB + so + i * sstep, gB + ko + i * gstep);
        }
    };

    load_stage(0, 0);
    asm volatile("cp.async.commit_group;");

    for (int it = 0; it < NCH; ++it) {
        const int s = it & 1;
        if (it + 1 < NCH) load_stage(it + 1, (it + 1) & 1);
        asm volatile("cp.async.commit_group;");
        asm volatile("cp.async.wait_group 1;");
        __syncthreads();

        const uint32_t* As = smem + (size_t)s * (STG / 4);
        const uint32_t* Bs = smem + 2 * (STG / 4) + (size_t)s * (STG / 4);
        #pragma unroll
        for (int kk = 0; kk < 4; ++kk) {
            const int kb = kk * 8;
            uint32_t af[2][4], bf[8][2];
            #pragma unroll
            for (int t = 0; t < 2; ++t) {
                const int r0 = warpM + t * 16 + g;
                af[t][0] = As[r0 * LDW + kb + c];
                af[t][1] = As[(r0 + 8) * LDW + kb + c];
                af[t][2] = As[r0 * LDW + kb + c + 4];
                af[t][3] = As[(r0 + 8) * LDW + kb + c + 4];
            }
            #pragma unroll
            for (int n = 0; n < 8; ++n) {
                const int nr = warpN + n * 8 + g;
                bf[n][0] = Bs[nr * LDW + kb + c];
                bf[n][1] = Bs[nr * LDW + kb + c + 4];
            }
            #pragma unroll
            for (int t = 0; t < 2; ++t)
                #pragma unroll
                for (int n = 0; n < 8; ++n)
                    mma_fp8(acc[t][n], af[t], bf[n]);
        }
        __syncthreads();
    }

    // ---- epilogue: symmetric hard mining, per-block candidate output ----
    float scj[16]; int tcj[16];
    #pragma unroll
    for (int n = 0; n < 8; ++n) {
        const int j0 = C + warpN + n * 8 + 2 * c;
        scj[2*n]   = g_sqq[j0];    scj[2*n+1] = g_sqq[j0 + 1];
        tcj[2*n]   = tw[ts * j0];  tcj[2*n+1] = tw[ts * (j0 + 1)];
    }
    float sqr4[4]; int tr4[4]; int rowi[4];
    #pragma unroll
    for (int t = 0; t < 2; ++t)
        #pragma unroll
        for (int p = 0; p < 2; ++p) {
            const int ri = R + warpM + t * 16 + p * 8 + g;
            rowi[t*2+p] = ri; sqr4[t*2+p] = g_sqq[ri]; tr4[t*2+p] = tw[ts * ri];
        }

    ull apr[4], anr[4], apc[16], anc[16];
    #pragma unroll
    for (int i = 0; i < 4; ++i)  { apr[i] = packv(0.0f, rowi[i]); anr[i] = 0xFFFFFFFFFFFFFFFFull; }
    #pragma unroll
    for (int n = 0; n < 8; ++n)
        #pragma unroll
        for (int e = 0; e < 2; ++e) {
            const int cj = n * 2 + e;
            apc[cj] = packv(0.0f, C + warpN + n * 8 + 2 * c + e);
            anc[cj] = 0xFFFFFFFFFFFFFFFFull;
        }

    #pragma unroll
    for (int t = 0; t < 2; ++t)
        #pragma unroll
        for (int n = 0; n < 8; ++n)
            #pragma unroll
            for (int p = 0; p < 2; ++p) {
                const int ri = t * 2 + p;
                #pragma unroll
                for (int e = 0; e < 2; ++e) {
                    const int cj = n * 2 + e;
                    const int jg = C + warpN + n * 8 + 2 * c + e;
                    const float d2 = fmaxf(fmaf(-2.f, acc[t][n][p * 2 + e], sqr4[ri] + scj[cj]), 0.f);
                    const ull pr = packv(d2, jg);
                    const ull pc = packv(d2, rowi[ri]);
                    if (tr4[ri] == tcj[cj]) {
                        if (pr > apr[ri]) apr[ri] = pr;
                        if (pc > apc[cj]) apc[cj] = pc;
                    } else {
                        if (pr < anr[ri]) anr[ri] = pr;
                        if (pc < anc[cj]) anc[cj] = pc;
                    }
                }
            }

    // warp-level reductions
    #pragma unroll
    for (int i = 0; i < 4; ++i) {
        #pragma unroll
        for (int m = 1; m <= 2; m <<= 1) {
            ull o;
            o = __shfl_xor_sync(0xffffffffu, apr[i], m); if (o > apr[i]) apr[i] = o;
            o = __shfl_xor_sync(0xffffffffu, anr[i], m); if (o < anr[i]) anr[i] = o;
        }
    }
    #pragma unroll
    for (int i = 0; i < 16; ++i) {
        #pragma unroll
        for (int m = 4; m <= 16; m <<= 1) {
            ull o;
            o = __shfl_xor_sync(0xffffffffu, apc[i], m); if (o > apc[i]) apc[i] = o;
            o = __shfl_xor_sync(0xffffffffu, anc[i], m); if (o < anc[i]) anc[i] = o;
        }
    }

    // block-level combine in (reused) smem, then plain global stores
    ull* s_rap = (ull*)smem;            // [128][2]
    ull* s_ran = s_rap + 256;           // [128][2]
    ull* s_cap = s_ran + 256;           // [128][4]
    ull* s_can = s_cap + 512;           // [128][4]
    const int colgrp = wid >> 2;
    const int mgrp   = wid & 3;

    if (c == 0) {
        #pragma unroll
        for (int i = 0; i < 4; ++i) {
            const int lr = warpM + (i >> 1) * 16 + (i & 1) * 8 + g;
            s_rap[lr * 2 + colgrp] = apr[i];
            s_ran[lr * 2 + colgrp] = anr[i];
        }
    }
    if (g == 0) {
        #pragma unroll
        for (int n = 0; n < 8; ++n)
            #pragma unroll
            for (int e = 0; e < 2; ++e) {
                const int lc = warpN + n * 8 + 2 * c + e;
                s_cap[lc * 4 + mgrp] = apc[n * 2 + e];
                s_can[lc * 4 + mgrp] = anc[n * 2 + e];
            }
    }
    __syncthreads();
    if (tid < 128) {
        ull a0 = s_rap[tid * 2], a1 = s_rap[tid * 2 + 1];
        ull b0 = s_ran[tid * 2], b1 = s_ran[tid * 2 + 1];
        g_posC[(size_t)(R + tid) * NB + bj] = a0 > a1 ? a0 : a1;
        g_negC[(size_t)(R + tid) * NB + bj] = b0 < b1 ? b0 : b1;
        if (bi != bj) {
            ull ca = s_cap[tid * 4], cn = s_can[tid * 4];
            #pragma unroll
            for (int q = 1; q < 4; ++q) {
                const ull ua = s_cap[tid * 4 + q], un = s_can[tid * 4 + q];
                if (ua > ca) ca = ua;
                if (un < cn) cn = un;
            }
            g_posC[(size_t)(C + tid) * NB + bi] = ca;
            g_negC[(size_t)(C + tid) * NB + bi] = cn;
        }
    }
}

// ---------------------------------------------------------------------------
// Refine: top-4 negative / top-2 positive block candidates, exact fp32 d2.
// One warp per row.
// ---------------------------------------------------------------------------
__global__ __launch_bounds__(256) void refine_kernel() {
    const int wid  = threadIdx.x >> 5;
    const int lane = threadIdx.x & 31;
    const int row  = blockIdx.x * 8 + wid;

    const ull* neg = &g_negC[(size_t)row * NB];
    const ull* pos = &g_posC[(size_t)row * NB];
    const float sqi = g_sq[row];
    const float4* xi = (const float4*)(g_x + (size_t)row * DIM);
    float4 xv[4];
    #pragma unroll
    for (int q = 0; q < 4; ++q) xv[q] = xi[q * 32 + lane];

    auto exact_d2 = [&](int j) -> float {
        const float4* xj = (const float4*)(g_x + (size_t)j * DIM);
        float dot = 0.f;
        #pragma unroll
        for (int q = 0; q < 4; ++q) {
            const float4 b = xj[q * 32 + lane];
            dot = fmaf(xv[q].x, b.x, fmaf(xv[q].y, b.y, fmaf(xv[q].z, b.z, fmaf(xv[q].w, b.w, dot))));
        }
        #pragma unroll
        for (int o = 16; o; o >>= 1) dot += __shfl_xor_sync(0xffffffffu, dot, o);
        return fmaf(-2.f, dot, sqi + g_sq[j]);
    };

    // negatives: top-4 smallest packed candidates, exact min
    ull c0 = neg[lane], c1 = neg[lane + 32];
    float an = CUDART_INF_F;
    #pragma unroll
    for (int k = 0; k < 4; ++k) {
        ull m = c0 < c1 ? c0 : c1;
        #pragma unroll
        for (int o = 16; o; o >>= 1) {
            const ull v = __shfl_xor_sync(0xffffffffu, m, o);
            if (v < m) m = v;
        }
        if (c0 == m) c0 = 0xFFFFFFFFFFFFFFFFull;
        else if (c1 == m) c1 = 0xFFFFFFFFFFFFFFFFull;
        if (m != 0xFFFFFFFFFFFFFFFFull) {
            const int j = (int)((unsigned)m & 8191u);
            an = fminf(an, exact_d2(j));
        }
    }

    // positives: top-2 largest packed candidates, exact max
    ull p0 = pos[lane], p1 = pos[lane + 32];
    float ap = 0.f;
    #pragma unroll
    for (int k = 0; k < 2; ++k) {
        ull m = p0 > p1 ? p0 : p1;
        #pragma unroll
        for (int o = 16; o; o >>= 1) {
            const ull v = __shfl_xor_sync(0xffffffffu, m, o);
            if (v > m) m = v;
        }
        if (p0 == m) p0 = 0ull;
        else if (p1 == m) p1 = 0ull;
        const int j = (int)((unsigned)m & 8191u);
        ap = fmaxf(ap, exact_d2(j));
    }

    if (lane == 0) {
        g_an2[row] = an;
        g_ap2[row] = ap;
    }
}

// ---------------------------------------------------------------------------
__global__ void loss_kernel(float* __restrict__ out) {
    __shared__ float red[32];
    const int t = threadIdx.x;  // 1024
    float s = 0.f;
    #pragma unroll
    for (int h = 0; h < 2; ++h) {
        const int i = t * 8 + h * 4;
        const float4 ap = *(const float4*)&g_ap2[i];
        const float4 an = *(const float4*)&g_an2[i];
        s += fmaxf(sqrtf(fmaxf(ap.x, 1e-12f)) - sqrtf(fmaxf(an.x, 1e-12f)) + 0.5f, 0.f);
        s += fmaxf(sqrtf(fmaxf(ap.y, 1e-12f)) - sqrtf(fmaxf(an.y, 1e-12f)) + 0.5f, 0.f);
        s += fmaxf(sqrtf(fmaxf(ap.z, 1e-12f)) - sqrtf(fmaxf(an.z, 1e-12f)) + 0.5f, 0.f);
        s += fmaxf(sqrtf(fmaxf(ap.w, 1e-12f)) - sqrtf(fmaxf(an.w, 1e-12f)) + 0.5f, 0.f);
    }
    #pragma unroll
    for (int o = 16; o; o >>= 1) s += __shfl_down_sync(0xffffffffu, s, o);
    if ((t & 31) == 0) red[t >> 5] = s;
    __syncthreads();
    if (t < 32) {
        float v = red[t];
        #pragma unroll
        for (int o = 16; o; o >>= 1) v += __shfl_down_sync(0xffffffffu, v, o);
        if (t == 0) out[0] = v * (1.0f / (float)NROWS);
    }
}

// ---------------------------------------------------------------------------
extern "C" void kernel_launch(void* const* d_in, const int* in_sizes, int n_in,
                              void* d_out, int out_size) {
    const float* inputs = (const float*)d_in[0];
    const float* A      = (const float*)d_in[1];
    const int*   tw     = (const int*)d_in[2];

    cudaFuncSetAttribute(gram_mma, cudaFuncAttributeMaxDynamicSharedMemorySize, SMEM_BYTES);

    detect_kernel<<<1, 1024>>>(tw);
    prep_kernel<<<NROWS, 128>>>(inputs, A);
    gram_mma<<<NBLK, 256, SMEM_BYTES>>>(tw);
    refine_kernel<<<NROWS / 8, 256>>>();
    loss_kernel<<<1, 1024>>>((float*)d_out);
}